// round 15
// baseline (speedup 1.0000x reference)
#include <cuda_runtime.h>
#include <math.h>

// ROI pooling, single ROI, POOL = 7x7, SCALE_FACTOR = 1.0  — FINAL (held)
// img: (1, 512, 512, 256) fp32 NHWC   -> d_in[0]
// roi: (1, 5) fp32 [_, x_min, y_min, x_max, y_max] -> d_in[1]
// out: (1, 256, 7, 7) fp32            -> d_out
//
// out[c*49 + py*7 + px] = img[((iy*512) + ix)*256 + c]
// iy = clip(y_min + floor(py * (h/7)), y_min, y_max), same for ix.
// Index math mirrors the JAX reference bit-exactly in fp32:
//   jnp.round -> rintf (round-half-to-even); h/7 in fp32;
//   floor == (int) truncation since py*(h/7) >= 0.
//
// Certification evidence (R4-R14, 7 passing samples of this source,
// across two physical containers):
//   timed {5.98, 6.14x3, 6.18x3}us; in-kernel 4.74-5.06us.
//   Distribution is stationary cross-container -> the floor is a
//   harness/launch-path property, not session-specific.
//   Floor decomposition: ~5.6us fixed launch/graph-replay overhead +
//   ~0.4us irreducible dependent chain (roi L2-hit -> fp32 index math
//   -> img L2-hit -> stores; img address is DATA-dependent on roi).
//   Roofline: DRAM 0.1%, L2 1.6%, issue 1.9% — every pipe idle; a 50KB
//   single-launch gather has no bandwidth/compute dimension to climb.
//   Shape sweep (in-kernel): 49x64 float4 best | 49x256 4.93 |
//   49x32 5.06 | 7x448 5.15. Closed-out alternatives: store-side
//   coalescing / smem or shuffle transpose (adds BAR/LDS latency to
//   save L2-absorbed scatter), multi-kernel split (extra graph node >=
//   whole body), input hardcoding (reseed-fragile, forbidden).
//
// Shape: one CTA per pooled pixel (49 CTAs on 49 SMs; wide-and-shallow
// wins for a latency chain — fatter/narrower CTAs both regressed).
// 64 threads each load one float4 of channels: a single coalesced 1KB
// LDG.128 burst per block on the critical path. Stores are stride-49
// scalar scatter into the 50KB output, fire-and-forget, merged in L2.

#define IMG_COLS 512
#define IMG_C    256
#define PH 7
#define PW 7

__global__ __launch_bounds__(64)
void roi_pool_kernel(const float4* __restrict__ img4,
                     const float*  __restrict__ roi,
                     float* __restrict__ out)
{
    const int p  = blockIdx.x;        // pooled pixel 0..48
    const int py = p / PW;
    const int px = p % PW;
    const int t  = threadIdx.x;       // channel group 0..63 (4 ch each)

    // roi[0..3] is 16B-aligned (buffer base) -> one LDG.128 plus one
    // scalar load, issued back-to-back (independent, MLP=2).
    const float4 r03 = *(const float4*)roi;   // {_, x_min, y_min, x_max}
    const float  r4  = roi[4];                //  y_max

    const int x_min = (int)rintf(r03.y);
    const int y_min = (int)rintf(r03.z);
    const int x_max = (int)rintf(r03.w);
    const int y_max = (int)rintf(r4);

    const float h = (float)(y_max - y_min + 1);
    const float w = (float)(x_max - x_min + 1);

    // Operands are non-negative: (int) truncation == floor.
    int iy = y_min + (int)((float)py * (h / 7.0f));
    int ix = x_min + (int)((float)px * (w / 7.0f));
    iy = min(max(iy, y_min), y_max);
    ix = min(max(ix, x_min), x_max);

    // One coalesced 16B load per thread: 64 threads x 16B = the
    // pixel's full 1KB channel vector.
    const float4 v = img4[((iy * IMG_COLS) + ix) * (IMG_C / 4) + t];

    // NCHW output: out[c*49 + p]; c = 4*t .. 4*t+3.
    const int base = (4 * t) * (PH * PW) + p;
    out[base]               = v.x;
    out[base + PH * PW]     = v.y;
    out[base + 2 * PH * PW] = v.z;
    out[base + 3 * PH * PW] = v.w;
}

extern "C" void kernel_launch(void* const* d_in, const int* in_sizes, int n_in,
                              void* d_out, int out_size)
{
    const float4* img4 = (const float4*)d_in[0];
    const float*  roi  = (const float*)d_in[1];
    float* out = (float*)d_out;

    roi_pool_kernel<<<PH * PW, 64>>>(img4, roi, out);
}

// round 16
// speedup vs baseline: 1.0052x; 1.0052x over previous
#include <cuda_runtime.h>
#include <math.h>

// ROI pooling, single ROI, POOL = 7x7, SCALE_FACTOR = 1.0  — FINAL (held)
// img: (1, 512, 512, 256) fp32 NHWC   -> d_in[0]
// roi: (1, 5) fp32 [_, x_min, y_min, x_max, y_max] -> d_in[1]
// out: (1, 256, 7, 7) fp32            -> d_out
//
// out[c*49 + py*7 + px] = img[((iy*512) + ix)*256 + c]
// iy = clip(y_min + floor(py * (h/7)), y_min, y_max), same for ix.
// Index math mirrors the JAX reference bit-exactly in fp32:
//   jnp.round -> rintf (round-half-to-even); h/7 in fp32;
//   floor == (int) truncation since py*(h/7) >= 0.
//
// Certification evidence (R4-R15, 8 passing samples of this source,
// across two physical containers):
//   timed {5.98, 6.14x3, 6.18x4}us; in-kernel 4.74-5.06us.
//   Stationary cross-container -> the floor is a harness/launch-path
//   property: ~5.6us fixed graph-replay/launch overhead + ~0.4us
//   irreducible dependent chain (roi L2-hit -> fp32 index math ->
//   img L2-hit -> stores; img address is DATA-dependent on roi).
//   The kernel body is ~7% of the timed window: even an empty body
//   would time > 5.5us. Roofline: DRAM 0.1%, L2 1.8%, issue 2.4% —
//   every pipe idle; a 50KB single-launch gather has no bandwidth or
//   compute dimension to climb.
//   Swept & closed: grid/block shape (49x64 float4 best of 4), vector
//   width (scalar/float4/2xfloat4), chain micro-cuts (floorf->cast;
//   clamp removal audited: provably dead but saves ~16cyc = 20x below
//   timer resolution), store-side coalescing / smem / shuffle
//   transposes (add BAR/LDS latency), multi-kernel split (extra graph
//   node >= whole body), input hardcoding (reseed-fragile, forbidden).
//
// Shape: one CTA per pooled pixel (49 CTAs on 49 SMs; wide-and-shallow
// wins for a latency chain — fatter/narrower CTAs both regressed).
// 64 threads each load one float4 of channels: a single coalesced 1KB
// LDG.128 burst per block on the critical path. Stores are stride-49
// scalar scatter into the 50KB output, fire-and-forget, merged in L2.

#define IMG_COLS 512
#define IMG_C    256
#define PH 7
#define PW 7

__global__ __launch_bounds__(64)
void roi_pool_kernel(const float4* __restrict__ img4,
                     const float*  __restrict__ roi,
                     float* __restrict__ out)
{
    const int p  = blockIdx.x;        // pooled pixel 0..48
    const int py = p / PW;
    const int px = p % PW;
    const int t  = threadIdx.x;       // channel group 0..63 (4 ch each)

    // roi[0..3] is 16B-aligned (buffer base) -> one LDG.128 plus one
    // scalar load, issued back-to-back (independent, MLP=2).
    const float4 r03 = *(const float4*)roi;   // {_, x_min, y_min, x_max}
    const float  r4  = roi[4];                //  y_max

    const int x_min = (int)rintf(r03.y);
    const int y_min = (int)rintf(r03.z);
    const int x_max = (int)rintf(r03.w);
    const int y_max = (int)rintf(r4);

    const float h = (float)(y_max - y_min + 1);
    const float w = (float)(x_max - x_min + 1);

    // Operands are non-negative: (int) truncation == floor.
    int iy = y_min + (int)((float)py * (h / 7.0f));
    int ix = x_min + (int)((float)px * (w / 7.0f));
    iy = min(max(iy, y_min), y_max);
    ix = min(max(ix, x_min), x_max);

    // One coalesced 16B load per thread: 64 threads x 16B = the
    // pixel's full 1KB channel vector.
    const float4 v = img4[((iy * IMG_COLS) + ix) * (IMG_C / 4) + t];

    // NCHW output: out[c*49 + p]; c = 4*t .. 4*t+3.
    const int base = (4 * t) * (PH * PW) + p;
    out[base]               = v.x;
    out[base + PH * PW]     = v.y;
    out[base + 2 * PH * PW] = v.z;
    out[base + 3 * PH * PW] = v.w;
}

extern "C" void kernel_launch(void* const* d_in, const int* in_sizes, int n_in,
                              void* d_out, int out_size)
{
    const float4* img4 = (const float4*)d_in[0];
    const float*  roi  = (const float*)d_in[1];
    float* out = (float*)d_out;

    roi_pool_kernel<<<PH * PW, 64>>>(img4, roi, out);
}